// round 5
// baseline (speedup 1.0000x reference)
#include <cuda_runtime.h>
#include <cuda_bf16.h>
#include <math.h>
#include <stdint.h>

#define BSZ 16
#define SEQ 2048
#define BQ  128
#define BK  64
#define NT  256
#define ST  72     // row stride (elems) Q/K/V tiles: 144B = 36 words -> conflict-free ldmatrix
#define RST 200    // row stride (elems) R window tile (192 data cols)
#define QWST 80    // row stride (floats) per-warp QW scatter buffer (max index 79)

typedef __nv_bfloat16 bf16;

// ---- smem byte offsets ----
// QW (8 warps * 16 * 80 * 4 = 40960 B) is UNIONED with the Q staging area
// (Qh+Ql = 36864 B): Q smem is only read during the prologue fragment load.
#define OFF_QW 0
#define OFF_QH 0
#define OFF_QL (OFF_QH + BQ*ST*2)          // 18432
#define OFF_KH 40960
#define OFF_KL (OFF_KH + BK*ST*2)
#define OFF_VH (OFF_KL + BK*ST*2)
#define OFF_VL (OFF_VH + BK*ST*2)
#define OFF_RH (OFF_VL + BK*ST*2)
#define SMEM_BYTES (OFF_RH + 64*RST*2)     // 103424 B -> 2 CTAs/SM
static_assert(SMEM_BYTES <= 113*1024, "smem too big for 2 CTAs/SM");

__device__ __forceinline__ uint32_t pk(__nv_bfloat16 a, __nv_bfloat16 b) {
    return (uint32_t)__bfloat16_as_ushort(a) | ((uint32_t)__bfloat16_as_ushort(b) << 16);
}
__device__ __forceinline__ void split4(float4 f, uint2 &h, uint2 &l) {
    __nv_bfloat16 hx=__float2bfloat16_rn(f.x), hy=__float2bfloat16_rn(f.y),
                  hz=__float2bfloat16_rn(f.z), hw=__float2bfloat16_rn(f.w);
    __nv_bfloat16 lx=__float2bfloat16_rn(f.x-__bfloat162float(hx)),
                  ly=__float2bfloat16_rn(f.y-__bfloat162float(hy)),
                  lz=__float2bfloat16_rn(f.z-__bfloat162float(hz)),
                  lw=__float2bfloat16_rn(f.w-__bfloat162float(hw));
    h.x=pk(hx,hy); h.y=pk(hz,hw); l.x=pk(lx,ly); l.y=pk(lz,lw);
}
__device__ __forceinline__ void ldmx4(uint32_t r[4], const void* p) {
    uint32_t a = (uint32_t)__cvta_generic_to_shared(p);
    asm volatile("ldmatrix.sync.aligned.m8n8.x4.shared.b16 {%0,%1,%2,%3}, [%4];\n"
                 : "=r"(r[0]),"=r"(r[1]),"=r"(r[2]),"=r"(r[3]) : "r"(a));
}
__device__ __forceinline__ void ldmx4t(uint32_t r[4], const void* p) {
    uint32_t a = (uint32_t)__cvta_generic_to_shared(p);
    asm volatile("ldmatrix.sync.aligned.m8n8.x4.trans.shared.b16 {%0,%1,%2,%3}, [%4];\n"
                 : "=r"(r[0]),"=r"(r[1]),"=r"(r[2]),"=r"(r[3]) : "r"(a));
}
__device__ __forceinline__ void mma(float c[4], const uint32_t a[4], uint32_t b0, uint32_t b1) {
    asm volatile("mma.sync.aligned.m16n8k16.row.col.f32.bf16.bf16.f32 "
                 "{%0,%1,%2,%3},{%4,%5,%6,%7},{%8,%9},{%0,%1,%2,%3};\n"
                 : "+f"(c[0]),"+f"(c[1]),"+f"(c[2]),"+f"(c[3])
                 : "r"(a[0]),"r"(a[1]),"r"(a[2]),"r"(a[3]),"r"(b0),"r"(b1));
}

__global__ __launch_bounds__(NT, 2)
void attn_relpos_mma(const float* __restrict__ Q, const float* __restrict__ K,
                     const float* __restrict__ V, const float* __restrict__ R,
                     float* __restrict__ O)
{
    extern __shared__ char smc[];
    float* QW = (float*)(smc + OFF_QW);
    bf16* Qh = (bf16*)(smc + OFF_QH);
    bf16* Ql = (bf16*)(smc + OFF_QL);
    bf16* Kh = (bf16*)(smc + OFF_KH);
    bf16* Kl = (bf16*)(smc + OFF_KL);
    bf16* Vh = (bf16*)(smc + OFF_VH);
    bf16* Vl = (bf16*)(smc + OFF_VL);
    bf16* Rh = (bf16*)(smc + OFF_RH);

    const int tid  = threadIdx.x;
    const int w    = tid >> 5;
    const int lane = tid & 31;
    const int g    = lane >> 2;    // row group 0..7
    const int tq   = lane & 3;     // col thread 0..3

    const int bq = (int)gridDim.x - 1 - (int)blockIdx.x;   // heavy CTAs first
    const int i0 = bq * BQ;
    const int b  = blockIdx.y;
    const int iw = i0 + w * 16;

    const float* Qb = Q + ((size_t)b * SEQ + i0) * 64;

    // ---- stage Q tile (prescaled by 1/8), hi/lo split ----
    #pragma unroll
    for (int r = 0; r < 8; ++r) {
        int idx = tid + r * NT;               // float4 index 0..2047
        int i = idx >> 4, d4 = (idx & 15) << 2;
        float4 f = *(const float4*)(Qb + i * 64 + d4);
        f.x *= 0.125f; f.y *= 0.125f; f.z *= 0.125f; f.w *= 0.125f;
        uint2 h, l; split4(f, h, l);
        *(uint2*)(Qh + i * ST + d4) = h;
        *(uint2*)(Ql + i * ST + d4) = l;
    }
    __syncthreads();

    // ---- preload Q A-fragments (held across whole loop) ----
    uint32_t qa_h[4][4], qa_l[4][4];
    {
        const int ar = w * 16 + (lane & 15);
        const int ac = (lane >> 4) << 3;
        #pragma unroll
        for (int kc = 0; kc < 4; ++kc) {
            ldmx4(qa_h[kc], Qh + ar * ST + kc * 16 + ac);
            ldmx4(qa_l[kc], Ql + ar * ST + kc * 16 + ac);
        }
    }

    float accO[8][4];
    #pragma unroll
    for (int nb = 0; nb < 8; ++nb)
        #pragma unroll
        for (int x = 0; x < 4; ++x) accO[nb][x] = 0.f;
    float m0 = -INFINITY, m1 = -INFINITY, l0 = 0.f, l1 = 0.f;

    float* QWw = QW + w * 16 * QWST;
    const int nkv = 2 * bq + 2;

    for (int t = 0; t < nkv; ++t) {
        const int j0 = t * BK;
        __syncthreads();   // Q frag preload (t=0) / previous-iter readers done

        // ---- stage K, V (hi/lo) ----
        const float* Kb = K + ((size_t)b * SEQ + j0) * 64;
        const float* Vb = V + ((size_t)b * SEQ + j0) * 64;
        #pragma unroll
        for (int r = 0; r < 4; ++r) {
            int idx = tid + r * NT;           // float4 index 0..1023
            int j = idx >> 4, d4 = (idx & 15) << 2;
            uint2 h, l;
            float4 fk = *(const float4*)(Kb + j * 64 + d4);
            split4(fk, h, l);
            *(uint2*)(Kh + j * ST + d4) = h;
            *(uint2*)(Kl + j * ST + d4) = l;
            float4 fv = *(const float4*)(Vb + j * 64 + d4);
            split4(fv, h, l);
            *(uint2*)(Vh + j * ST + d4) = h;
            *(uint2*)(Vl + j * ST + d4) = l;
        }
        // ---- stage R window (hi only): Rh[d][v], v = c - cwin0 ----
        const int cwin0 = SEQ - 128 - i0 + j0;
        #pragma unroll
        for (int r = 0; r < 12; ++r) {
            int idx = tid + r * NT;           // float4 index 0..3071
            int d = idx / 48, v4 = (idx % 48) << 2;
            int c = cwin0 + v4;
            float4 f = make_float4(0.f, 0.f, 0.f, 0.f);
            if (c < SEQ) f = *(const float4*)(R + (size_t)d * SEQ + c);
            uint2 h;
            h.x = pk(__float2bfloat16_rn(f.x), __float2bfloat16_rn(f.y));
            h.y = pk(__float2bfloat16_rn(f.z), __float2bfloat16_rn(f.w));
            *(uint2*)(Rh + d * RST + v4) = h;
        }
        __syncthreads();

        if (j0 <= iw + 15) {   // warp has at least one unmasked row
            // ---- bias GEMM: QW[il][u] = Q(rows) . R(window cols), hi-pass ----
            const int v0w = 112 - 16 * w;
            const int trow = ((lane >> 4) << 3) + (lane & 7);   // trans k-row part
            const int tcol = ((lane >> 3) & 1) << 3;            // trans n-col part
            #pragma unroll
            for (int np = 0; np < 5; ++np) {
                float cw0[4] = {0.f,0.f,0.f,0.f}, cw1[4] = {0.f,0.f,0.f,0.f};
                #pragma unroll
                for (int kc = 0; kc < 4; ++kc) {
                    uint32_t rb[4];
                    ldmx4t(rb, Rh + (kc * 16 + trow) * RST + v0w + np * 16 + tcol);
                    mma(cw0, qa_h[kc], rb[0], rb[2]);
                    mma(cw1, qa_h[kc], rb[1], rb[3]);
                }
                const int uc = np * 16 + 2 * tq;
                *(float2*)(QWw + g * QWST + uc)           = make_float2(cw0[0], cw0[1]);
                *(float2*)(QWw + (g + 8) * QWST + uc)     = make_float2(cw0[2], cw0[3]);
                *(float2*)(QWw + g * QWST + uc + 8)       = make_float2(cw1[0], cw1[1]);
                *(float2*)(QWw + (g + 8) * QWST + uc + 8) = make_float2(cw1[2], cw1[3]);
            }
            __syncwarp();

            // ---- S GEMM (3-pass) ----
            float sc[8][4];
            #pragma unroll
            for (int nb = 0; nb < 8; ++nb)
                #pragma unroll
                for (int x = 0; x < 4; ++x) sc[nb][x] = 0.f;
            {
                const int br = lane & 15;
                const int bc = (lane >> 4) << 3;
                #pragma unroll
                for (int np = 0; np < 4; ++np) {
                    #pragma unroll
                    for (int kc = 0; kc < 4; ++kc) {
                        uint32_t kh[4], kl[4];
                        ldmx4(kh, Kh + (np * 16 + br) * ST + kc * 16 + bc);
                        ldmx4(kl, Kl + (np * 16 + br) * ST + kc * 16 + bc);
                        mma(sc[2*np],   qa_h[kc], kh[0], kh[2]);
                        mma(sc[2*np+1], qa_h[kc], kh[1], kh[3]);
                        mma(sc[2*np],   qa_h[kc], kl[0], kl[2]);
                        mma(sc[2*np+1], qa_h[kc], kl[1], kl[3]);
                        mma(sc[2*np],   qa_l[kc], kh[0], kh[2]);
                        mma(sc[2*np+1], qa_l[kc], kh[1], kh[3]);
                    }
                }
            }

            // ---- add skewed bias from QW buffer ----
            #pragma unroll
            for (int nb = 0; nb < 8; ++nb) {
                int u0 = 8 * nb + 2 * tq + 15 - g;   // row g
                int u1 = 8 * nb + 2 * tq + 7 - g;    // row g+8
                sc[nb][0] += QWw[g * QWST + u0];
                sc[nb][1] += QWw[g * QWST + u0 + 1];
                sc[nb][2] += QWw[(g + 8) * QWST + u1];
                sc[nb][3] += QWw[(g + 8) * QWST + u1 + 1];
            }

            // ---- causal mask ----
            if (j0 + 63 > iw) {
                const int ia = iw + g, ib = iw + 8 + g;
                #pragma unroll
                for (int nb = 0; nb < 8; ++nb) {
                    int j = j0 + 8 * nb + 2 * tq;
                    if (j     > ia) sc[nb][0] = -INFINITY;
                    if (j + 1 > ia) sc[nb][1] = -INFINITY;
                    if (j     > ib) sc[nb][2] = -INFINITY;
                    if (j + 1 > ib) sc[nb][3] = -INFINITY;
                }
            }

            // ---- online softmax (rows g / g+8) ----
            float mx0 = -INFINITY, mx1 = -INFINITY;
            #pragma unroll
            for (int nb = 0; nb < 8; ++nb) {
                mx0 = fmaxf(mx0, fmaxf(sc[nb][0], sc[nb][1]));
                mx1 = fmaxf(mx1, fmaxf(sc[nb][2], sc[nb][3]));
            }
            mx0 = fmaxf(mx0, __shfl_xor_sync(0xffffffffu, mx0, 1));
            mx0 = fmaxf(mx0, __shfl_xor_sync(0xffffffffu, mx0, 2));
            mx1 = fmaxf(mx1, __shfl_xor_sync(0xffffffffu, mx1, 1));
            mx1 = fmaxf(mx1, __shfl_xor_sync(0xffffffffu, mx1, 2));
            const float mn0 = fmaxf(m0, mx0), mn1 = fmaxf(m1, mx1);
            const float cor0 = __expf(m0 - mn0), cor1 = __expf(m1 - mn1);
            m0 = mn0; m1 = mn1;
            float ps0 = 0.f, ps1 = 0.f;
            #pragma unroll
            for (int nb = 0; nb < 8; ++nb) {
                sc[nb][0] = __expf(sc[nb][0] - mn0); ps0 += sc[nb][0];
                sc[nb][1] = __expf(sc[nb][1] - mn0); ps0 += sc[nb][1];
                sc[nb][2] = __expf(sc[nb][2] - mn1); ps1 += sc[nb][2];
                sc[nb][3] = __expf(sc[nb][3] - mn1); ps1 += sc[nb][3];
            }
            ps0 += __shfl_xor_sync(0xffffffffu, ps0, 1);
            ps0 += __shfl_xor_sync(0xffffffffu, ps0, 2);
            ps1 += __shfl_xor_sync(0xffffffffu, ps1, 1);
            ps1 += __shfl_xor_sync(0xffffffffu, ps1, 2);
            l0 = l0 * cor0 + ps0;
            l1 = l1 * cor1 + ps1;
            #pragma unroll
            for (int nb = 0; nb < 8; ++nb) {
                accO[nb][0] *= cor0; accO[nb][1] *= cor0;
                accO[nb][2] *= cor1; accO[nb][3] *= cor1;
            }

            // ---- PV GEMM (3-pass), P register-direct ----
            #pragma unroll
            for (int kc = 0; kc < 4; ++kc) {
                uint32_t pah[4], pal[4];
                #pragma unroll
                for (int q = 0; q < 4; ++q) {
                    const int nb = 2 * kc + (q >> 1);
                    const int r0 = (q & 1) ? 2 : 0;
                    float p0 = sc[nb][r0], p1 = sc[nb][r0 + 1];
                    __nv_bfloat16 h0 = __float2bfloat16_rn(p0), h1 = __float2bfloat16_rn(p1);
                    pah[(q >> 1) * 2 + (q & 1)] = pk(h0, h1);
                    pal[(q >> 1) * 2 + (q & 1)] =
                        pk(__float2bfloat16_rn(p0 - __bfloat162float(h0)),
                           __float2bfloat16_rn(p1 - __bfloat162float(h1)));
                }
                #pragma unroll
                for (int np = 0; np < 4; ++np) {
                    uint32_t vh[4], vl[4];
                    ldmx4t(vh, Vh + (kc * 16 + trow) * ST + np * 16 + tcol);
                    ldmx4t(vl, Vl + (kc * 16 + trow) * ST + np * 16 + tcol);
                    mma(accO[2*np],   pah, vh[0], vh[2]);
                    mma(accO[2*np+1], pah, vh[1], vh[3]);
                    mma(accO[2*np],   pal, vh[0], vh[2]);
                    mma(accO[2*np+1], pal, vh[1], vh[3]);
                    mma(accO[2*np],   pah, vl[0], vl[2]);
                    mma(accO[2*np+1], pah, vl[1], vl[3]);
                }
            }
        }
    }

    // ---- epilogue ----
    const float inv0 = 1.0f / l0, inv1 = 1.0f / l1;
    float* Ob = O + ((size_t)b * SEQ + iw) * 64;
    #pragma unroll
    for (int nb = 0; nb < 8; ++nb) {
        const int dc = 8 * nb + 2 * tq;
        *(float2*)(Ob + g * 64 + dc)       = make_float2(accO[nb][0] * inv0, accO[nb][1] * inv0);
        *(float2*)(Ob + (g + 8) * 64 + dc) = make_float2(accO[nb][2] * inv1, accO[nb][3] * inv1);
    }
}

extern "C" void kernel_launch(void* const* d_in, const int* in_sizes, int n_in,
                              void* d_out, int out_size)
{
    const float* Q = (const float*)d_in[0];
    const float* K = (const float*)d_in[1];
    const float* V = (const float*)d_in[2];
    const float* R = (const float*)d_in[3];
    float* O = (float*)d_out;

    cudaFuncSetAttribute(attn_relpos_mma,
                         cudaFuncAttributeMaxDynamicSharedMemorySize, SMEM_BYTES);
    dim3 grid(SEQ / BQ, BSZ);   // 16 x 16
    attn_relpos_mma<<<grid, NT, SMEM_BYTES>>>(Q, K, V, R, O);
}

// round 6
// speedup vs baseline: 1.5069x; 1.5069x over previous
#include <cuda_runtime.h>
#include <cuda_bf16.h>
#include <math.h>
#include <stdint.h>

#define BSZ 16
#define SEQ 2048
#define BQ  128
#define BK  64
#define NT  256
#define ST  72     // row stride (elems) K/V tiles: 144B -> conflict-free ldmatrix
#define RST 200    // row stride (elems) R window tile (192 data cols)
#define QWST 80    // row stride (floats) per-warp QW scatter buffer
#define RPAD 2240  // padded R row length (2048 + 192 zero tail)

typedef __nv_bfloat16 bf16;

// ---- preconverted global operands (bf16) ----
__device__ bf16 g_Kh[BSZ * SEQ * 64];
__device__ bf16 g_Kl[BSZ * SEQ * 64];
__device__ bf16 g_Vh[BSZ * SEQ * 64];
__device__ bf16 g_Vl[BSZ * SEQ * 64];
__device__ bf16 g_Rh[64 * RPAD];

// ---- smem layout ----
// [0, 40960): QW scatter (8 warps * 16 * 80 * 4) UNIONED with Q hi/lo staging (36864)
// two stage buffers, each: Kh,Kl,Vh,Vl (4 * 64*72*2 = 36864) + Rh (64*200*2 = 25600) = 62464
#define OFF_QW 0
#define OFF_QH 0
#define OFF_QL (OFF_QH + BQ*ST*2)
#define OFF_ST0 40960
#define STG_K  0
#define STG_KL (64*ST*2)
#define STG_V  (2*64*ST*2)
#define STG_VL (3*64*ST*2)
#define STG_R  (4*64*ST*2)
#define STAGE_BYTES (4*64*ST*2 + 64*RST*2)   // 62464
#define SMEM_BYTES (OFF_ST0 + 2*STAGE_BYTES) // 165888
static_assert(SMEM_BYTES <= 227*1024, "smem");

__device__ __forceinline__ uint32_t pk(bf16 a, bf16 b) {
    return (uint32_t)__bfloat16_as_ushort(a) | ((uint32_t)__bfloat16_as_ushort(b) << 16);
}
__device__ __forceinline__ void split4(float4 f, uint2 &h, uint2 &l) {
    bf16 hx=__float2bfloat16_rn(f.x), hy=__float2bfloat16_rn(f.y),
         hz=__float2bfloat16_rn(f.z), hw=__float2bfloat16_rn(f.w);
    bf16 lx=__float2bfloat16_rn(f.x-__bfloat162float(hx)),
         ly=__float2bfloat16_rn(f.y-__bfloat162float(hy)),
         lz=__float2bfloat16_rn(f.z-__bfloat162float(hz)),
         lw=__float2bfloat16_rn(f.w-__bfloat162float(hw));
    h.x=pk(hx,hy); h.y=pk(hz,hw); l.x=pk(lx,ly); l.y=pk(lz,lw);
}
__device__ __forceinline__ void ldmx4(uint32_t r[4], const void* p) {
    uint32_t a = (uint32_t)__cvta_generic_to_shared(p);
    asm volatile("ldmatrix.sync.aligned.m8n8.x4.shared.b16 {%0,%1,%2,%3}, [%4];\n"
                 : "=r"(r[0]),"=r"(r[1]),"=r"(r[2]),"=r"(r[3]) : "r"(a));
}
__device__ __forceinline__ void ldmx4t(uint32_t r[4], const void* p) {
    uint32_t a = (uint32_t)__cvta_generic_to_shared(p);
    asm volatile("ldmatrix.sync.aligned.m8n8.x4.trans.shared.b16 {%0,%1,%2,%3}, [%4];\n"
                 : "=r"(r[0]),"=r"(r[1]),"=r"(r[2]),"=r"(r[3]) : "r"(a));
}
__device__ __forceinline__ void mma(float c[4], const uint32_t a[4], uint32_t b0, uint32_t b1) {
    asm volatile("mma.sync.aligned.m16n8k16.row.col.f32.bf16.bf16.f32 "
                 "{%0,%1,%2,%3},{%4,%5,%6,%7},{%8,%9},{%0,%1,%2,%3};\n"
                 : "+f"(c[0]),"+f"(c[1]),"+f"(c[2]),"+f"(c[3])
                 : "r"(a[0]),"r"(a[1]),"r"(a[2]),"r"(a[3]),"r"(b0),"r"(b1));
}
__device__ __forceinline__ void cpa16(void* dst, const void* src) {
    uint32_t d = (uint32_t)__cvta_generic_to_shared(dst);
    asm volatile("cp.async.cg.shared.global [%0], [%1], 16;\n" :: "r"(d), "l"(src));
}
__device__ __forceinline__ void cpa_commit() { asm volatile("cp.async.commit_group;\n"); }

// ======== pre-convert kernel ========
__global__ void preconvert(const float* __restrict__ K, const float* __restrict__ V,
                           const float* __restrict__ R)
{
    const int stride = gridDim.x * blockDim.x;
    const int tid0 = blockIdx.x * blockDim.x + threadIdx.x;
    // K,V: 16*2048*64 / 4 = 524288 float4 chunks
    for (int i = tid0; i < BSZ*SEQ*16; i += stride) {
        const int e = i * 4;
        uint2 h, l;
        split4(*(const float4*)(K + e), h, l);
        *(uint2*)(g_Kh + e) = h; *(uint2*)(g_Kl + e) = l;
        split4(*(const float4*)(V + e), h, l);
        *(uint2*)(g_Vh + e) = h; *(uint2*)(g_Vl + e) = l;
    }
    // R: 64 rows x 2240 (pad tail with zeros); 8 cols per thread
    for (int i = tid0; i < 64*RPAD/8; i += stride) {
        const int d = i / (RPAD/8), m = i % (RPAD/8);
        const int c = m * 8;
        uint2 h0 = make_uint2(0u, 0u), h1 = make_uint2(0u, 0u);
        if (c + 8 <= SEQ) {
            float4 f0 = *(const float4*)(R + (size_t)d * SEQ + c);
            float4 f1 = *(const float4*)(R + (size_t)d * SEQ + c + 4);
            h0.x = pk(__float2bfloat16_rn(f0.x), __float2bfloat16_rn(f0.y));
            h0.y = pk(__float2bfloat16_rn(f0.z), __float2bfloat16_rn(f0.w));
            h1.x = pk(__float2bfloat16_rn(f1.x), __float2bfloat16_rn(f1.y));
            h1.y = pk(__float2bfloat16_rn(f1.z), __float2bfloat16_rn(f1.w));
        }
        *(uint2*)(g_Rh + (size_t)d * RPAD + c) = h0;
        *(uint2*)(g_Rh + (size_t)d * RPAD + c + 4) = h1;
    }
}

// ======== main kernel ========
__global__ __launch_bounds__(NT, 1)
void attn_relpos_mma(const float* __restrict__ Q, float* __restrict__ O)
{
    extern __shared__ char smc[];
    float* QW = (float*)(smc + OFF_QW);
    bf16* Qh = (bf16*)(smc + OFF_QH);
    bf16* Ql = (bf16*)(smc + OFF_QL);

    const int tid  = threadIdx.x;
    const int w    = tid >> 5;
    const int lane = tid & 31;
    const int g    = lane >> 2;
    const int tq   = lane & 3;

    const int bq = (int)gridDim.x - 1 - (int)blockIdx.x;   // heavy CTAs first
    const int i0 = bq * BQ;
    const int b  = blockIdx.y;
    const int iw = i0 + w * 16;

    const float* Qb = Q + ((size_t)b * SEQ + i0) * 64;

    // ---- stage Q tile (prescaled by 1/8), hi/lo split ----
    #pragma unroll
    for (int r = 0; r < 8; ++r) {
        int idx = tid + r * NT;
        int i = idx >> 4, d4 = (idx & 15) << 2;
        float4 f = *(const float4*)(Qb + i * 64 + d4);
        f.x *= 0.125f; f.y *= 0.125f; f.z *= 0.125f; f.w *= 0.125f;
        uint2 h, l; split4(f, h, l);
        *(uint2*)(Qh + i * ST + d4) = h;
        *(uint2*)(Ql + i * ST + d4) = l;
    }
    __syncthreads();

    // ---- preload persistent Q A-fragments ----
    uint32_t qa_h[4][4], qa_l[4][4];
    {
        const int ar = w * 16 + (lane & 15);
        const int ac = (lane >> 4) << 3;
        #pragma unroll
        for (int kc = 0; kc < 4; ++kc) {
            ldmx4(qa_h[kc], Qh + ar * ST + kc * 16 + ac);
            ldmx4(qa_l[kc], Ql + ar * ST + kc * 16 + ac);
        }
    }

    const int nkv = 2 * bq + 2;

    // ---- cp.async stage issuer ----
    // K/V: 8 chunks/thread: r=0..7, tile=r>>1 (Kh,Kl,Vh,Vl), row/col from tid
    // R: 6 chunks/thread
    const int kv_row = ((tid) >> 3) & 31;       // combined with r parity below
    auto issue_stage = [&](int t) {
        char* sb = smc + OFF_ST0 + (t & 1) * STAGE_BYTES;
        const int j0 = t * BK;
        const size_t kvbase = ((size_t)b * SEQ + j0) * 64;
        const bf16* gsrc[4] = { g_Kh + kvbase, g_Kl + kvbase, g_Vh + kvbase, g_Vl + kvbase };
        char* sdst[4] = { sb + STG_K, sb + STG_KL, sb + STG_V, sb + STG_VL };
        #pragma unroll
        for (int r = 0; r < 8; ++r) {
            const int q = tid + r * NT;
            const int tile = r >> 1;
            const int row = (q >> 3) & 63;
            const int c8 = (q & 7) * 8;
            cpa16(sdst[tile] + (row * ST + c8) * 2, gsrc[tile] + row * 64 + c8);
        }
        const int cwin0 = SEQ - 128 - i0 + j0;   // >= 0, multiple of 64
        #pragma unroll
        for (int r = 0; r < 6; ++r) {
            const int q = tid + r * NT;
            const int d = q / 24, m = q % 24;
            cpa16(sb + STG_R + (d * RST + m * 8) * 2,
                  g_Rh + (size_t)d * RPAD + cwin0 + m * 8);
        }
        cpa_commit();
    };

    float accO[8][4];
    #pragma unroll
    for (int nb = 0; nb < 8; ++nb)
        #pragma unroll
        for (int x = 0; x < 4; ++x) accO[nb][x] = 0.f;
    float m0 = -INFINITY, m1 = -INFINITY, l0 = 0.f, l1 = 0.f;

    float* QWw = QW + w * 16 * QWST;

    issue_stage(0);

    for (int t = 0; t < nkv; ++t) {
        const int j0 = t * BK;
        if (t + 1 < nkv) {
            issue_stage(t + 1);
            asm volatile("cp.async.wait_group 1;\n");
        } else {
            asm volatile("cp.async.wait_group 0;\n");
        }
        __syncthreads();   // stage t visible to all; also gates QW after Q-frag preload

        char* sb = smc + OFF_ST0 + (t & 1) * STAGE_BYTES;
        bf16* Kh = (bf16*)(sb + STG_K);
        bf16* Kl = (bf16*)(sb + STG_KL);
        bf16* Vh = (bf16*)(sb + STG_V);
        bf16* Vl = (bf16*)(sb + STG_VL);
        bf16* Rh = (bf16*)(sb + STG_R);

        if (j0 <= iw + 15) {
            // ---- bias GEMM: QW = Q . R(window), hi-pass ----
            const int v0w = 112 - 16 * w;
            const int trow = ((lane >> 4) << 3) + (lane & 7);
            const int tcol = ((lane >> 3) & 1) << 3;
            #pragma unroll
            for (int np = 0; np < 5; ++np) {
                float cw0[4] = {0.f,0.f,0.f,0.f}, cw1[4] = {0.f,0.f,0.f,0.f};
                #pragma unroll
                for (int kc = 0; kc < 4; ++kc) {
                    uint32_t rb[4];
                    ldmx4t(rb, Rh + (kc * 16 + trow) * RST + v0w + np * 16 + tcol);
                    mma(cw0, qa_h[kc], rb[0], rb[2]);
                    mma(cw1, qa_h[kc], rb[1], rb[3]);
                }
                const int uc = np * 16 + 2 * tq;
                *(float2*)(QWw + g * QWST + uc)           = make_float2(cw0[0], cw0[1]);
                *(float2*)(QWw + (g + 8) * QWST + uc)     = make_float2(cw0[2], cw0[3]);
                *(float2*)(QWw + g * QWST + uc + 8)       = make_float2(cw1[0], cw1[1]);
                *(float2*)(QWw + (g + 8) * QWST + uc + 8) = make_float2(cw1[2], cw1[3]);
            }
            __syncwarp();

            // ---- S GEMM (3-pass) ----
            float sc[8][4];
            #pragma unroll
            for (int nb = 0; nb < 8; ++nb)
                #pragma unroll
                for (int x = 0; x < 4; ++x) sc[nb][x] = 0.f;
            {
                const int br = lane & 15;
                const int bc = (lane >> 4) << 3;
                #pragma unroll
                for (int np = 0; np < 4; ++np) {
                    #pragma unroll
                    for (int kc = 0; kc < 4; ++kc) {
                        uint32_t kh[4], kl[4];
                        ldmx4(kh, Kh + (np * 16 + br) * ST + kc * 16 + bc);
                        ldmx4(kl, Kl + (np * 16 + br) * ST + kc * 16 + bc);
                        mma(sc[2*np],   qa_h[kc], kh[0], kh[2]);
                        mma(sc[2*np+1], qa_h[kc], kh[1], kh[3]);
                        mma(sc[2*np],   qa_h[kc], kl[0], kl[2]);
                        mma(sc[2*np+1], qa_h[kc], kl[1], kl[3]);
                        mma(sc[2*np],   qa_l[kc], kh[0], kh[2]);
                        mma(sc[2*np+1], qa_l[kc], kh[1], kh[3]);
                    }
                }
            }

            // ---- add skewed bias ----
            #pragma unroll
            for (int nb = 0; nb < 8; ++nb) {
                int u0 = 8 * nb + 2 * tq + 15 - g;
                int u1 = 8 * nb + 2 * tq + 7 - g;
                sc[nb][0] += QWw[g * QWST + u0];
                sc[nb][1] += QWw[g * QWST + u0 + 1];
                sc[nb][2] += QWw[(g + 8) * QWST + u1];
                sc[nb][3] += QWw[(g + 8) * QWST + u1 + 1];
            }

            // ---- causal mask ----
            if (j0 + 63 > iw) {
                const int ia = iw + g, ib = iw + 8 + g;
                #pragma unroll
                for (int nb = 0; nb < 8; ++nb) {
                    int j = j0 + 8 * nb + 2 * tq;
                    if (j     > ia) sc[nb][0] = -INFINITY;
                    if (j + 1 > ia) sc[nb][1] = -INFINITY;
                    if (j     > ib) sc[nb][2] = -INFINITY;
                    if (j + 1 > ib) sc[nb][3] = -INFINITY;
                }
            }

            // ---- online softmax ----
            float mx0 = -INFINITY, mx1 = -INFINITY;
            #pragma unroll
            for (int nb = 0; nb < 8; ++nb) {
                mx0 = fmaxf(mx0, fmaxf(sc[nb][0], sc[nb][1]));
                mx1 = fmaxf(mx1, fmaxf(sc[nb][2], sc[nb][3]));
            }
            mx0 = fmaxf(mx0, __shfl_xor_sync(0xffffffffu, mx0, 1));
            mx0 = fmaxf(mx0, __shfl_xor_sync(0xffffffffu, mx0, 2));
            mx1 = fmaxf(mx1, __shfl_xor_sync(0xffffffffu, mx1, 1));
            mx1 = fmaxf(mx1, __shfl_xor_sync(0xffffffffu, mx1, 2));
            const float mn0 = fmaxf(m0, mx0), mn1 = fmaxf(m1, mx1);
            const float cor0 = __expf(m0 - mn0), cor1 = __expf(m1 - mn1);
            m0 = mn0; m1 = mn1;
            float ps0 = 0.f, ps1 = 0.f;
            #pragma unroll
            for (int nb = 0; nb < 8; ++nb) {
                sc[nb][0] = __expf(sc[nb][0] - mn0); ps0 += sc[nb][0];
                sc[nb][1] = __expf(sc[nb][1] - mn0); ps0 += sc[nb][1];
                sc[nb][2] = __expf(sc[nb][2] - mn1); ps1 += sc[nb][2];
                sc[nb][3] = __expf(sc[nb][3] - mn1); ps1 += sc[nb][3];
            }
            ps0 += __shfl_xor_sync(0xffffffffu, ps0, 1);
            ps0 += __shfl_xor_sync(0xffffffffu, ps0, 2);
            ps1 += __shfl_xor_sync(0xffffffffu, ps1, 1);
            ps1 += __shfl_xor_sync(0xffffffffu, ps1, 2);
            l0 = l0 * cor0 + ps0;
            l1 = l1 * cor1 + ps1;
            #pragma unroll
            for (int nb = 0; nb < 8; ++nb) {
                accO[nb][0] *= cor0; accO[nb][1] *= cor0;
                accO[nb][2] *= cor1; accO[nb][3] *= cor1;
            }

            // ---- PV GEMM (3-pass), P register-direct ----
            #pragma unroll
            for (int kc = 0; kc < 4; ++kc) {
                uint32_t pah[4], pal[4];
                #pragma unroll
                for (int q = 0; q < 4; ++q) {
                    const int nb = 2 * kc + (q >> 1);
                    const int r0 = (q & 1) ? 2 : 0;
                    float p0 = sc[nb][r0], p1 = sc[nb][r0 + 1];
                    bf16 h0 = __float2bfloat16_rn(p0), h1 = __float2bfloat16_rn(p1);
                    pah[(q >> 1) * 2 + (q & 1)] = pk(h0, h1);
                    pal[(q >> 1) * 2 + (q & 1)] =
                        pk(__float2bfloat16_rn(p0 - __bfloat162float(h0)),
                           __float2bfloat16_rn(p1 - __bfloat162float(h1)));
                }
                #pragma unroll
                for (int np = 0; np < 4; ++np) {
                    uint32_t vh[4], vl[4];
                    ldmx4t(vh, Vh + (kc * 16 + trow) * ST + np * 16 + tcol);
                    ldmx4t(vl, Vl + (kc * 16 + trow) * ST + np * 16 + tcol);
                    mma(accO[2*np],   pah, vh[0], vh[2]);
                    mma(accO[2*np+1], pah, vh[1], vh[3]);
                    mma(accO[2*np],   pal, vh[0], vh[2]);
                    mma(accO[2*np+1], pal, vh[1], vh[3]);
                    mma(accO[2*np],   pah, vl[0], vl[2]);
                    mma(accO[2*np+1], pah, vl[1], vl[3]);
                }
            }
        }
        __syncthreads();   // all reads of stage t done before it is overwritten at t+2
    }

    // ---- epilogue ----
    const float inv0 = 1.0f / l0, inv1 = 1.0f / l1;
    float* Ob = O + ((size_t)b * SEQ + iw) * 64;
    #pragma unroll
    for (int nb = 0; nb < 8; ++nb) {
        const int dc = 8 * nb + 2 * tq;
        *(float2*)(Ob + g * 64 + dc)       = make_float2(accO[nb][0] * inv0, accO[nb][1] * inv0);
        *(float2*)(Ob + (g + 8) * 64 + dc) = make_float2(accO[nb][2] * inv1, accO[nb][3] * inv1);
    }
}

extern "C" void kernel_launch(void* const* d_in, const int* in_sizes, int n_in,
                              void* d_out, int out_size)
{
    const float* Q = (const float*)d_in[0];
    const float* K = (const float*)d_in[1];
    const float* V = (const float*)d_in[2];
    const float* R = (const float*)d_in[3];
    float* O = (float*)d_out;

    preconvert<<<1024, 256>>>(K, V, R);

    cudaFuncSetAttribute(attn_relpos_mma,
                         cudaFuncAttributeMaxDynamicSharedMemorySize, SMEM_BYTES);
    dim3 grid(SEQ / BQ, BSZ);   // 16 x 16
    attn_relpos_mma<<<grid, NT, SMEM_BYTES>>>(Q, O);
}

// round 7
// speedup vs baseline: 1.8862x; 1.2518x over previous
#include <cuda_runtime.h>
#include <cuda_fp16.h>
#include <math.h>
#include <stdint.h>

#define BSZ 16
#define SEQ 2048
#define BQ  128
#define BK  64
#define NT  256
#define ST  72     // row stride (halves) K/V tiles: 144B -> conflict-free ldmatrix
#define RST 200    // row stride (halves) R window tile (192 data cols)
#define QWST 80    // row stride (floats) per-warp QW scatter buffer
#define RPAD 2240  // padded R row length (2048 + 192 zero tail)

// ---- preconverted global operands (fp16) ----
__device__ __half g_K[BSZ * SEQ * 64];
__device__ __half g_V[BSZ * SEQ * 64];
__device__ __half g_R[64 * RPAD];

// ---- smem layout (bytes) ----
// [0, 40960): QW fp32 scatter (8 warps*16*80*4) UNIONED with Q fp16 staging (18432)
// [40960, 59392): KV stage 0   (Kh 9216 + Vh 9216)
// [59392, 77824): KV stage 1
// [77824, 103424): R window (single buffer, 64*200*2)
#define OFF_QW 0
#define OFF_QS 0
#define OFF_KV0 40960
#define KV_STAGE 18432
#define STG_V  9216
#define OFF_R  (OFF_KV0 + 2*KV_STAGE)
#define SMEM_BYTES (OFF_R + 64*RST*2)   // 103424 -> 2 CTAs/SM
static_assert(SMEM_BYTES <= 113*1024, "smem too big for 2 CTAs/SM");

__device__ __forceinline__ uint32_t pkh(float a, float b) {
    __half2 h = __floats2half2_rn(a, b);
    return *(uint32_t*)&h;
}
__device__ __forceinline__ void ldmx4(uint32_t r[4], const void* p) {
    uint32_t a = (uint32_t)__cvta_generic_to_shared(p);
    asm volatile("ldmatrix.sync.aligned.m8n8.x4.shared.b16 {%0,%1,%2,%3}, [%4];\n"
                 : "=r"(r[0]),"=r"(r[1]),"=r"(r[2]),"=r"(r[3]) : "r"(a));
}
__device__ __forceinline__ void ldmx4t(uint32_t r[4], const void* p) {
    uint32_t a = (uint32_t)__cvta_generic_to_shared(p);
    asm volatile("ldmatrix.sync.aligned.m8n8.x4.trans.shared.b16 {%0,%1,%2,%3}, [%4];\n"
                 : "=r"(r[0]),"=r"(r[1]),"=r"(r[2]),"=r"(r[3]) : "r"(a));
}
__device__ __forceinline__ void mma(float c[4], const uint32_t a[4], uint32_t b0, uint32_t b1) {
    asm volatile("mma.sync.aligned.m16n8k16.row.col.f32.f16.f16.f32 "
                 "{%0,%1,%2,%3},{%4,%5,%6,%7},{%8,%9},{%0,%1,%2,%3};\n"
                 : "+f"(c[0]),"+f"(c[1]),"+f"(c[2]),"+f"(c[3])
                 : "r"(a[0]),"r"(a[1]),"r"(a[2]),"r"(a[3]),"r"(b0),"r"(b1));
}
__device__ __forceinline__ void cpa16(void* dst, const void* src) {
    uint32_t d = (uint32_t)__cvta_generic_to_shared(dst);
    asm volatile("cp.async.cg.shared.global [%0], [%1], 16;\n" :: "r"(d), "l"(src));
}
__device__ __forceinline__ void cpa_commit() { asm volatile("cp.async.commit_group;\n"); }

// ======== pre-convert kernel: K,V,R -> fp16 ========
__global__ void preconvert(const float* __restrict__ K, const float* __restrict__ V,
                           const float* __restrict__ R)
{
    const int stride = gridDim.x * blockDim.x;
    const int tid0 = blockIdx.x * blockDim.x + threadIdx.x;
    for (int i = tid0; i < BSZ*SEQ*16; i += stride) {
        const int e = i * 4;
        float4 fk = *(const float4*)(K + e);
        float4 fv = *(const float4*)(V + e);
        *(uint2*)(g_K + e) = make_uint2(pkh(fk.x, fk.y), pkh(fk.z, fk.w));
        *(uint2*)(g_V + e) = make_uint2(pkh(fv.x, fv.y), pkh(fv.z, fv.w));
    }
    for (int i = tid0; i < 64*RPAD/8; i += stride) {
        const int d = i / (RPAD/8), m = i % (RPAD/8);
        const int c = m * 8;
        uint2 h0 = make_uint2(0u, 0u), h1 = make_uint2(0u, 0u);
        if (c + 8 <= SEQ) {
            float4 f0 = *(const float4*)(R + (size_t)d * SEQ + c);
            float4 f1 = *(const float4*)(R + (size_t)d * SEQ + c + 4);
            h0 = make_uint2(pkh(f0.x, f0.y), pkh(f0.z, f0.w));
            h1 = make_uint2(pkh(f1.x, f1.y), pkh(f1.z, f1.w));
        }
        *(uint2*)(g_R + (size_t)d * RPAD + c) = h0;
        *(uint2*)(g_R + (size_t)d * RPAD + c + 4) = h1;
    }
}

// ======== main kernel ========
__global__ __launch_bounds__(NT, 2)
void attn_relpos_mma(const float* __restrict__ Q, float* __restrict__ O)
{
    extern __shared__ char smc[];
    float* QW = (float*)(smc + OFF_QW);
    __half* Qs = (__half*)(smc + OFF_QS);

    const int tid  = threadIdx.x;
    const int w    = tid >> 5;
    const int lane = tid & 31;
    const int g    = lane >> 2;
    const int tq   = lane & 3;

    const int bq = (int)gridDim.x - 1 - (int)blockIdx.x;   // heavy CTAs first
    const int i0 = bq * BQ;
    const int b  = blockIdx.y;
    const int iw = i0 + w * 16;
    const int nkv = 2 * bq + 2;

    // ---- cp.async issuers ----
    auto issue_kv = [&](int t) {
        char* sb = smc + OFF_KV0 + (t & 1) * KV_STAGE;
        const size_t kvbase = ((size_t)b * SEQ + (size_t)t * BK) * 64;
        #pragma unroll
        for (int r = 0; r < 4; ++r) {
            const int q = (tid + (r & 1) * NT);          // 0..511
            const int row = q >> 3, c8 = (q & 7) * 8;
            const __half* src = (r < 2 ? g_K : g_V) + kvbase + row * 64 + c8;
            char* dst = sb + (r < 2 ? 0 : STG_V) + (row * ST + c8) * 2;
            cpa16(dst, src);
        }
    };
    auto issue_r = [&](int t) {
        const int cwin0 = SEQ - 128 - i0 + t * BK;       // >= 0
        #pragma unroll
        for (int r = 0; r < 6; ++r) {
            const int q = tid + r * NT;                  // 0..1535
            const int d = q / 24, m = q % 24;
            cpa16(smc + OFF_R + (d * RST + m * 8) * 2,
                  g_R + (size_t)d * RPAD + cwin0 + m * 8);
        }
    };

    issue_kv(0); issue_r(0); cpa_commit();               // G0

    // ---- stage Q tile (prescaled by 1/8) to fp16 smem ----
    const float* Qb = Q + ((size_t)b * SEQ + i0) * 64;
    #pragma unroll
    for (int r = 0; r < 8; ++r) {
        int idx = tid + r * NT;
        int i = idx >> 4, d4 = (idx & 15) << 2;
        float4 f = *(const float4*)(Qb + i * 64 + d4);
        *(uint2*)(Qs + i * ST + d4) =
            make_uint2(pkh(f.x * 0.125f, f.y * 0.125f), pkh(f.z * 0.125f, f.w * 0.125f));
    }
    __syncthreads();

    // ---- preload persistent Q A-fragments ----
    uint32_t qa[4][4];
    {
        const int ar = w * 16 + (lane & 15);
        const int ac = (lane >> 4) << 3;
        #pragma unroll
        for (int kc = 0; kc < 4; ++kc)
            ldmx4(qa[kc], Qs + ar * ST + kc * 16 + ac);
    }

    float accO[8][4];
    #pragma unroll
    for (int nb = 0; nb < 8; ++nb)
        #pragma unroll
        for (int x = 0; x < 4; ++x) accO[nb][x] = 0.f;
    float m0 = -INFINITY, m1 = -INFINITY, l0 = 0.f, l1 = 0.f;

    float* QWw = QW + w * 16 * QWST;
    const int trow = ((lane >> 4) << 3) + (lane & 7);
    const int tcol = ((lane >> 3) & 1) << 3;

    for (int t = 0; t < nkv; ++t) {
        const int j0 = t * BK;
        if (t + 1 < nkv) {
            issue_kv(t + 1); cpa_commit();
            asm volatile("cp.async.wait_group 1;\n");
        } else {
            asm volatile("cp.async.wait_group 0;\n");
        }
        __syncthreads();   // stage t (KV + R) visible; Q-frag preload done before QW writes

        char* sb = smc + OFF_KV0 + (t & 1) * KV_STAGE;
        __half* Kh = (__half*)sb;
        __half* Vh = (__half*)(sb + STG_V);
        __half* Rh = (__half*)(smc + OFF_R);

        const bool active = (j0 <= iw + 15);

        // ---- bias GEMM: QW = Q . R(window cols), fp16 single pass ----
        if (active) {
            const int v0w = 112 - 16 * w;
            #pragma unroll
            for (int np = 0; np < 5; ++np) {
                float cw0[4] = {0.f,0.f,0.f,0.f}, cw1[4] = {0.f,0.f,0.f,0.f};
                #pragma unroll
                for (int kc = 0; kc < 4; ++kc) {
                    uint32_t rb[4];
                    ldmx4t(rb, Rh + (kc * 16 + trow) * RST + v0w + np * 16 + tcol);
                    mma(cw0, qa[kc], rb[0], rb[2]);
                    mma(cw1, qa[kc], rb[1], rb[3]);
                }
                const int uc = np * 16 + 2 * tq;
                *(float2*)(QWw + g * QWST + uc)           = make_float2(cw0[0], cw0[1]);
                *(float2*)(QWw + (g + 8) * QWST + uc)     = make_float2(cw0[2], cw0[3]);
                *(float2*)(QWw + g * QWST + uc + 8)       = make_float2(cw1[0], cw1[1]);
                *(float2*)(QWw + (g + 8) * QWST + uc + 8) = make_float2(cw1[2], cw1[3]);
            }
        }
        __syncthreads();   // all R reads done -> safe to overwrite R buffer
        if (t + 1 < nkv) { issue_r(t + 1); cpa_commit(); }

        if (active) {
            __syncwarp();
            // ---- S GEMM (single fp16 pass) ----
            float sc[8][4];
            #pragma unroll
            for (int nb = 0; nb < 8; ++nb)
                #pragma unroll
                for (int x = 0; x < 4; ++x) sc[nb][x] = 0.f;
            {
                const int br = lane & 15;
                const int bc = (lane >> 4) << 3;
                #pragma unroll
                for (int np = 0; np < 4; ++np) {
                    #pragma unroll
                    for (int kc = 0; kc < 4; ++kc) {
                        uint32_t kh[4];
                        ldmx4(kh, Kh + (np * 16 + br) * ST + kc * 16 + bc);
                        mma(sc[2*np],   qa[kc], kh[0], kh[2]);
                        mma(sc[2*np+1], qa[kc], kh[1], kh[3]);
                    }
                }
            }

            // ---- add skewed bias ----
            #pragma unroll
            for (int nb = 0; nb < 8; ++nb) {
                int u0 = 8 * nb + 2 * tq + 15 - g;
                int u1 = 8 * nb + 2 * tq + 7 - g;
                sc[nb][0] += QWw[g * QWST + u0];
                sc[nb][1] += QWw[g * QWST + u0 + 1];
                sc[nb][2] += QWw[(g + 8) * QWST + u1];
                sc[nb][3] += QWw[(g + 8) * QWST + u1 + 1];
            }

            // ---- causal mask ----
            if (j0 + 63 > iw) {
                const int ia = iw + g, ib = iw + 8 + g;
                #pragma unroll
                for (int nb = 0; nb < 8; ++nb) {
                    int j = j0 + 8 * nb + 2 * tq;
                    if (j     > ia) sc[nb][0] = -INFINITY;
                    if (j + 1 > ia) sc[nb][1] = -INFINITY;
                    if (j     > ib) sc[nb][2] = -INFINITY;
                    if (j + 1 > ib) sc[nb][3] = -INFINITY;
                }
            }

            // ---- online softmax ----
            float mx0 = -INFINITY, mx1 = -INFINITY;
            #pragma unroll
            for (int nb = 0; nb < 8; ++nb) {
                mx0 = fmaxf(mx0, fmaxf(sc[nb][0], sc[nb][1]));
                mx1 = fmaxf(mx1, fmaxf(sc[nb][2], sc[nb][3]));
            }
            mx0 = fmaxf(mx0, __shfl_xor_sync(0xffffffffu, mx0, 1));
            mx0 = fmaxf(mx0, __shfl_xor_sync(0xffffffffu, mx0, 2));
            mx1 = fmaxf(mx1, __shfl_xor_sync(0xffffffffu, mx1, 1));
            mx1 = fmaxf(mx1, __shfl_xor_sync(0xffffffffu, mx1, 2));
            const float mn0 = fmaxf(m0, mx0), mn1 = fmaxf(m1, mx1);
            const float cor0 = __expf(m0 - mn0), cor1 = __expf(m1 - mn1);
            m0 = mn0; m1 = mn1;
            float ps0 = 0.f, ps1 = 0.f;
            #pragma unroll
            for (int nb = 0; nb < 8; ++nb) {
                sc[nb][0] = __expf(sc[nb][0] - mn0); ps0 += sc[nb][0];
                sc[nb][1] = __expf(sc[nb][1] - mn0); ps0 += sc[nb][1];
                sc[nb][2] = __expf(sc[nb][2] - mn1); ps1 += sc[nb][2];
                sc[nb][3] = __expf(sc[nb][3] - mn1); ps1 += sc[nb][3];
            }
            ps0 += __shfl_xor_sync(0xffffffffu, ps0, 1);
            ps0 += __shfl_xor_sync(0xffffffffu, ps0, 2);
            ps1 += __shfl_xor_sync(0xffffffffu, ps1, 1);
            ps1 += __shfl_xor_sync(0xffffffffu, ps1, 2);
            l0 = l0 * cor0 + ps0;
            l1 = l1 * cor1 + ps1;
            #pragma unroll
            for (int nb = 0; nb < 8; ++nb) {
                accO[nb][0] *= cor0; accO[nb][1] *= cor0;
                accO[nb][2] *= cor1; accO[nb][3] *= cor1;
            }

            // ---- PV GEMM (single fp16 pass), P register-direct ----
            #pragma unroll
            for (int kc = 0; kc < 4; ++kc) {
                uint32_t pa[4];
                #pragma unroll
                for (int q = 0; q < 4; ++q) {
                    const int nb = 2 * kc + (q >> 1);
                    const int r0 = (q & 1) ? 2 : 0;
                    pa[(q >> 1) * 2 + (q & 1)] = pkh(sc[nb][r0], sc[nb][r0 + 1]);
                }
                #pragma unroll
                for (int np = 0; np < 4; ++np) {
                    uint32_t vh[4];
                    ldmx4t(vh, Vh + (kc * 16 + trow) * ST + np * 16 + tcol);
                    mma(accO[2*np],   pa, vh[0], vh[2]);
                    mma(accO[2*np+1], pa, vh[1], vh[3]);
                }
            }
        }
        __syncthreads();   // all KV-stage-t & QW reads done before overwrite
    }

    // ---- epilogue ----
    const float inv0 = 1.0f / l0, inv1 = 1.0f / l1;
    float* Ob = O + ((size_t)b * SEQ + iw) * 64;
    #pragma unroll
    for (int nb = 0; nb < 8; ++nb) {
        const int dc = 8 * nb + 2 * tq;
        *(float2*)(Ob + g * 64 + dc)       = make_float2(accO[nb][0] * inv0, accO[nb][1] * inv0);
        *(float2*)(Ob + (g + 8) * 64 + dc) = make_float2(accO[nb][2] * inv1, accO[nb][3] * inv1);
    }
}

extern "C" void kernel_launch(void* const* d_in, const int* in_sizes, int n_in,
                              void* d_out, int out_size)
{
    const float* Q = (const float*)d_in[0];
    const float* K = (const float*)d_in[1];
    const float* V = (const float*)d_in[2];
    const float* R = (const float*)d_in[3];
    float* O = (float*)d_out;

    preconvert<<<1024, 256>>>(K, V, R);

    cudaFuncSetAttribute(attn_relpos_mma,
                         cudaFuncAttributeMaxDynamicSharedMemorySize, SMEM_BYTES);
    dim3 grid(SEQ / BQ, BSZ);   // 16 x 16
    attn_relpos_mma<<<grid, NT, SMEM_BYTES>>>(Q, O);
}

// round 8
// speedup vs baseline: 2.8196x; 1.4948x over previous
#include <cuda_runtime.h>
#include <cuda_fp16.h>
#include <math.h>
#include <stdint.h>

#define BSZ 16
#define SEQ 2048
#define BQ  128
#define BK  64
#define NT  256
#define ST  72     // row stride (halves) K/V tiles: 144B -> conflict-free ldmatrix
#define RST 200    // row stride (halves) R window tile (192 data cols)
#define QWST 80    // row stride (floats) per-warp QW scatter buffer
#define RPAD 2240  // padded R row length (2048 + 192 zero tail)
#define CHUNK 8    // KV tiles per CTA chunk

// ---- preconverted global operands (fp16) ----
__device__ __half g_K[BSZ * SEQ * 64];
__device__ __half g_V[BSZ * SEQ * 64];
__device__ __half g_R[64 * RPAD];

// ---- split-KV partial scratch ----
__device__ float g_pO[BSZ * 16 * 4 * BQ * 64];   // 33.5 MB
__device__ float g_pm[BSZ * 16 * 4 * BQ];
__device__ float g_pl[BSZ * 16 * 4 * BQ];

// chunk schedule: heavy (bq large) first
__constant__ uint8_t c_bq[40] = {15,15,15,15, 14,14,14,14, 13,13,13,13, 12,12,12,12,
                                 11,11,11, 10,10,10, 9,9,9, 8,8,8,
                                 7,7, 6,6, 5,5, 4,4, 3, 2, 1, 0};
__constant__ uint8_t c_ch[40] = {0,1,2,3, 0,1,2,3, 0,1,2,3, 0,1,2,3,
                                 0,1,2, 0,1,2, 0,1,2, 0,1,2,
                                 0,1, 0,1, 0,1, 0,1, 0, 0, 0, 0};
__constant__ uint8_t c_nc[16] = {1,1,1,1,2,2,2,2,3,3,3,3,4,4,4,4};

// ---- smem layout (bytes) ----
#define OFF_QW 0
#define OFF_QS 0
#define OFF_KV0 40960
#define KV_STAGE 18432
#define STG_V  9216
#define OFF_R  (OFF_KV0 + 2*KV_STAGE)
#define SMEM_BYTES (OFF_R + 64*RST*2)   // 103424 -> 2 CTAs/SM
static_assert(SMEM_BYTES <= 113*1024, "smem too big for 2 CTAs/SM");

__device__ __forceinline__ uint32_t pkh(float a, float b) {
    __half2 h = __floats2half2_rn(a, b);
    return *(uint32_t*)&h;
}
__device__ __forceinline__ void ldmx4(uint32_t r[4], const void* p) {
    uint32_t a = (uint32_t)__cvta_generic_to_shared(p);
    asm volatile("ldmatrix.sync.aligned.m8n8.x4.shared.b16 {%0,%1,%2,%3}, [%4];\n"
                 : "=r"(r[0]),"=r"(r[1]),"=r"(r[2]),"=r"(r[3]) : "r"(a));
}
__device__ __forceinline__ void ldmx4t(uint32_t r[4], const void* p) {
    uint32_t a = (uint32_t)__cvta_generic_to_shared(p);
    asm volatile("ldmatrix.sync.aligned.m8n8.x4.trans.shared.b16 {%0,%1,%2,%3}, [%4];\n"
                 : "=r"(r[0]),"=r"(r[1]),"=r"(r[2]),"=r"(r[3]) : "r"(a));
}
__device__ __forceinline__ void mma(float c[4], const uint32_t a[4], uint32_t b0, uint32_t b1) {
    asm volatile("mma.sync.aligned.m16n8k16.row.col.f32.f16.f16.f32 "
                 "{%0,%1,%2,%3},{%4,%5,%6,%7},{%8,%9},{%0,%1,%2,%3};\n"
                 : "+f"(c[0]),"+f"(c[1]),"+f"(c[2]),"+f"(c[3])
                 : "r"(a[0]),"r"(a[1]),"r"(a[2]),"r"(a[3]),"r"(b0),"r"(b1));
}
__device__ __forceinline__ void cpa16(void* dst, const void* src) {
    uint32_t d = (uint32_t)__cvta_generic_to_shared(dst);
    asm volatile("cp.async.cg.shared.global [%0], [%1], 16;\n" :: "r"(d), "l"(src));
}
__device__ __forceinline__ void cpa_commit() { asm volatile("cp.async.commit_group;\n"); }

// ======== pre-convert kernel: K,V,R -> fp16 ========
__global__ void preconvert(const float* __restrict__ K, const float* __restrict__ V,
                           const float* __restrict__ R)
{
    const int stride = gridDim.x * blockDim.x;
    const int tid0 = blockIdx.x * blockDim.x + threadIdx.x;
    for (int i = tid0; i < BSZ*SEQ*16; i += stride) {
        const int e = i * 4;
        float4 fk = *(const float4*)(K + e);
        float4 fv = *(const float4*)(V + e);
        *(uint2*)(g_K + e) = make_uint2(pkh(fk.x, fk.y), pkh(fk.z, fk.w));
        *(uint2*)(g_V + e) = make_uint2(pkh(fv.x, fv.y), pkh(fv.z, fv.w));
    }
    for (int i = tid0; i < 64*RPAD/8; i += stride) {
        const int d = i / (RPAD/8), m = i % (RPAD/8);
        const int c = m * 8;
        uint2 h0 = make_uint2(0u, 0u), h1 = make_uint2(0u, 0u);
        if (c + 8 <= SEQ) {
            float4 f0 = *(const float4*)(R + (size_t)d * SEQ + c);
            float4 f1 = *(const float4*)(R + (size_t)d * SEQ + c + 4);
            h0 = make_uint2(pkh(f0.x, f0.y), pkh(f0.z, f0.w));
            h1 = make_uint2(pkh(f1.x, f1.y), pkh(f1.z, f1.w));
        }
        *(uint2*)(g_R + (size_t)d * RPAD + c) = h0;
        *(uint2*)(g_R + (size_t)d * RPAD + c + 4) = h1;
    }
}

// ======== main kernel: one KV chunk per CTA ========
__global__ __launch_bounds__(NT, 2)
void attn_relpos_mma(const float* __restrict__ Q)
{
    extern __shared__ char smc[];
    float* QW = (float*)(smc + OFF_QW);
    __half* Qs = (__half*)(smc + OFF_QS);

    const int tid  = threadIdx.x;
    const int w    = tid >> 5;
    const int lane = tid & 31;
    const int g    = lane >> 2;
    const int tq   = lane & 3;

    const int bq = c_bq[blockIdx.x];
    const int ch = c_ch[blockIdx.x];
    const int b  = blockIdx.y;
    const int i0 = bq * BQ;
    const int iw = i0 + w * 16;
    const int nkv = 2 * bq + 2;
    const int tstart = ch * CHUNK;
    const int tend = min(tstart + CHUNK, nkv);
    const int pidx = (b * 16 + bq) * 4 + ch;

    // ---- cp.async issuers ----
    auto issue_kv = [&](int t) {
        char* sb = smc + OFF_KV0 + (t & 1) * KV_STAGE;
        const size_t kvbase = ((size_t)b * SEQ + (size_t)t * BK) * 64;
        #pragma unroll
        for (int r = 0; r < 4; ++r) {
            const int q = (tid + (r & 1) * NT);
            const int row = q >> 3, c8 = (q & 7) * 8;
            const __half* src = (r < 2 ? g_K : g_V) + kvbase + row * 64 + c8;
            char* dst = sb + (r < 2 ? 0 : STG_V) + (row * ST + c8) * 2;
            cpa16(dst, src);
        }
    };
    auto issue_r = [&](int t) {
        const int cwin0 = SEQ - 128 - i0 + t * BK;       // >= 0
        #pragma unroll
        for (int r = 0; r < 6; ++r) {
            const int q = tid + r * NT;
            const int d = q / 24, m = q % 24;
            cpa16(smc + OFF_R + (d * RST + m * 8) * 2,
                  g_R + (size_t)d * RPAD + cwin0 + m * 8);
        }
    };

    issue_kv(tstart); issue_r(tstart); cpa_commit();

    // ---- stage Q tile (prescaled by 1/8) to fp16 smem ----
    const float* Qb = Q + ((size_t)b * SEQ + i0) * 64;
    #pragma unroll
    for (int r = 0; r < 8; ++r) {
        int idx = tid + r * NT;
        int i = idx >> 4, d4 = (idx & 15) << 2;
        float4 f = *(const float4*)(Qb + i * 64 + d4);
        *(uint2*)(Qs + i * ST + d4) =
            make_uint2(pkh(f.x * 0.125f, f.y * 0.125f), pkh(f.z * 0.125f, f.w * 0.125f));
    }
    __syncthreads();

    // ---- preload persistent Q A-fragments ----
    uint32_t qa[4][4];
    {
        const int ar = w * 16 + (lane & 15);
        const int ac = (lane >> 4) << 3;
        #pragma unroll
        for (int kc = 0; kc < 4; ++kc)
            ldmx4(qa[kc], Qs + ar * ST + kc * 16 + ac);
    }

    float accO[8][4];
    #pragma unroll
    for (int nb = 0; nb < 8; ++nb)
        #pragma unroll
        for (int x = 0; x < 4; ++x) accO[nb][x] = 0.f;
    float m0 = -INFINITY, m1 = -INFINITY, l0 = 0.f, l1 = 0.f;

    float* QWw = QW + w * 16 * QWST;
    const int trow = ((lane >> 4) << 3) + (lane & 7);
    const int tcol = ((lane >> 3) & 1) << 3;

    for (int t = tstart; t < tend; ++t) {
        const int j0 = t * BK;
        if (t + 1 < tend) {
            issue_kv(t + 1); cpa_commit();
            asm volatile("cp.async.wait_group 1;\n");
        } else {
            asm volatile("cp.async.wait_group 0;\n");
        }
        __syncthreads();

        char* sb = smc + OFF_KV0 + (t & 1) * KV_STAGE;
        __half* Kh = (__half*)sb;
        __half* Vh = (__half*)(sb + STG_V);
        __half* Rh = (__half*)(smc + OFF_R);

        const bool active = (j0 <= iw + 15);

        // ---- bias GEMM: QW = Q . R(window cols) ----
        if (active) {
            const int v0w = 112 - 16 * w;
            #pragma unroll
            for (int np = 0; np < 5; ++np) {
                float cw0[4] = {0.f,0.f,0.f,0.f}, cw1[4] = {0.f,0.f,0.f,0.f};
                #pragma unroll
                for (int kc = 0; kc < 4; ++kc) {
                    uint32_t rb[4];
                    ldmx4t(rb, Rh + (kc * 16 + trow) * RST + v0w + np * 16 + tcol);
                    mma(cw0, qa[kc], rb[0], rb[2]);
                    mma(cw1, qa[kc], rb[1], rb[3]);
                }
                const int uc = np * 16 + 2 * tq;
                *(float2*)(QWw + g * QWST + uc)           = make_float2(cw0[0], cw0[1]);
                *(float2*)(QWw + (g + 8) * QWST + uc)     = make_float2(cw0[2], cw0[3]);
                *(float2*)(QWw + g * QWST + uc + 8)       = make_float2(cw1[0], cw1[1]);
                *(float2*)(QWw + (g + 8) * QWST + uc + 8) = make_float2(cw1[2], cw1[3]);
            }
        }
        __syncthreads();   // all R reads done -> safe to overwrite R buffer
        if (t + 1 < tend) { issue_r(t + 1); cpa_commit(); }

        if (active) {
            __syncwarp();
            // ---- S GEMM ----
            float sc[8][4];
            #pragma unroll
            for (int nb = 0; nb < 8; ++nb)
                #pragma unroll
                for (int x = 0; x < 4; ++x) sc[nb][x] = 0.f;
            {
                const int br = lane & 15;
                const int bc = (lane >> 4) << 3;
                #pragma unroll
                for (int np = 0; np < 4; ++np) {
                    #pragma unroll
                    for (int kc = 0; kc < 4; ++kc) {
                        uint32_t kh[4];
                        ldmx4(kh, Kh + (np * 16 + br) * ST + kc * 16 + bc);
                        mma(sc[2*np],   qa[kc], kh[0], kh[2]);
                        mma(sc[2*np+1], qa[kc], kh[1], kh[3]);
                    }
                }
            }

            // ---- add skewed bias ----
            #pragma unroll
            for (int nb = 0; nb < 8; ++nb) {
                int u0 = 8 * nb + 2 * tq + 15 - g;
                int u1 = 8 * nb + 2 * tq + 7 - g;
                sc[nb][0] += QWw[g * QWST + u0];
                sc[nb][1] += QWw[g * QWST + u0 + 1];
                sc[nb][2] += QWw[(g + 8) * QWST + u1];
                sc[nb][3] += QWw[(g + 8) * QWST + u1 + 1];
            }

            // ---- causal mask ----
            if (j0 + 63 > iw) {
                const int ia = iw + g, ib = iw + 8 + g;
                #pragma unroll
                for (int nb = 0; nb < 8; ++nb) {
                    int j = j0 + 8 * nb + 2 * tq;
                    if (j     > ia) sc[nb][0] = -INFINITY;
                    if (j + 1 > ia) sc[nb][1] = -INFINITY;
                    if (j     > ib) sc[nb][2] = -INFINITY;
                    if (j + 1 > ib) sc[nb][3] = -INFINITY;
                }
            }

            // ---- online softmax ----
            float mx0 = -INFINITY, mx1 = -INFINITY;
            #pragma unroll
            for (int nb = 0; nb < 8; ++nb) {
                mx0 = fmaxf(mx0, fmaxf(sc[nb][0], sc[nb][1]));
                mx1 = fmaxf(mx1, fmaxf(sc[nb][2], sc[nb][3]));
            }
            mx0 = fmaxf(mx0, __shfl_xor_sync(0xffffffffu, mx0, 1));
            mx0 = fmaxf(mx0, __shfl_xor_sync(0xffffffffu, mx0, 2));
            mx1 = fmaxf(mx1, __shfl_xor_sync(0xffffffffu, mx1, 1));
            mx1 = fmaxf(mx1, __shfl_xor_sync(0xffffffffu, mx1, 2));
            const float mn0 = fmaxf(m0, mx0), mn1 = fmaxf(m1, mx1);
            const float cor0 = __expf(m0 - mn0), cor1 = __expf(m1 - mn1);
            m0 = mn0; m1 = mn1;
            float ps0 = 0.f, ps1 = 0.f;
            #pragma unroll
            for (int nb = 0; nb < 8; ++nb) {
                sc[nb][0] = __expf(sc[nb][0] - mn0); ps0 += sc[nb][0];
                sc[nb][1] = __expf(sc[nb][1] - mn0); ps0 += sc[nb][1];
                sc[nb][2] = __expf(sc[nb][2] - mn1); ps1 += sc[nb][2];
                sc[nb][3] = __expf(sc[nb][3] - mn1); ps1 += sc[nb][3];
            }
            ps0 += __shfl_xor_sync(0xffffffffu, ps0, 1);
            ps0 += __shfl_xor_sync(0xffffffffu, ps0, 2);
            ps1 += __shfl_xor_sync(0xffffffffu, ps1, 1);
            ps1 += __shfl_xor_sync(0xffffffffu, ps1, 2);
            l0 = l0 * cor0 + ps0;
            l1 = l1 * cor1 + ps1;
            #pragma unroll
            for (int nb = 0; nb < 8; ++nb) {
                accO[nb][0] *= cor0; accO[nb][1] *= cor0;
                accO[nb][2] *= cor1; accO[nb][3] *= cor1;
            }

            // ---- PV GEMM, P register-direct ----
            #pragma unroll
            for (int kc = 0; kc < 4; ++kc) {
                uint32_t pa[4];
                #pragma unroll
                for (int q = 0; q < 4; ++q) {
                    const int nb = 2 * kc + (q >> 1);
                    const int r0 = (q & 1) ? 2 : 0;
                    pa[(q >> 1) * 2 + (q & 1)] = pkh(sc[nb][r0], sc[nb][r0 + 1]);
                }
                #pragma unroll
                for (int np = 0; np < 4; ++np) {
                    uint32_t vh[4];
                    ldmx4t(vh, Vh + (kc * 16 + trow) * ST + np * 16 + tcol);
                    mma(accO[2*np],   pa, vh[0], vh[2]);
                    mma(accO[2*np+1], pa, vh[1], vh[3]);
                }
            }
        }
        __syncthreads();
    }

    // ---- epilogue: write unnormalized partials ----
    float* Pb = g_pO + (size_t)pidx * (BQ * 64);
    const int r0 = w * 16 + g, r1 = r0 + 8;
    #pragma unroll
    for (int nb = 0; nb < 8; ++nb) {
        const int dc = 8 * nb + 2 * tq;
        *(float2*)(Pb + r0 * 64 + dc) = make_float2(accO[nb][0], accO[nb][1]);
        *(float2*)(Pb + r1 * 64 + dc) = make_float2(accO[nb][2], accO[nb][3]);
    }
    if (tq == 0) {
        g_pm[pidx * BQ + r0] = m0;  g_pl[pidx * BQ + r0] = l0;
        g_pm[pidx * BQ + r1] = m1;  g_pl[pidx * BQ + r1] = l1;
    }
}

// ======== combine kernel: merge <=4 partials per row ========
__global__ __launch_bounds__(NT)
void combine(float* __restrict__ O)
{
    const int bq = blockIdx.x, b = blockIdx.y;
    const int nc = c_nc[bq];
    const int tid = threadIdx.x;
    const int row = tid >> 1;
    const int col0 = (tid & 1) * 32;
    const int pbase = (b * 16 + bq) * 4;

    float M = -INFINITY, mv[4];
    for (int c = 0; c < nc; ++c) {
        mv[c] = g_pm[(pbase + c) * BQ + row];
        M = fmaxf(M, mv[c]);
    }
    float L = 0.f, wc[4];
    for (int c = 0; c < nc; ++c) {
        wc[c] = __expf(mv[c] - M);
        L += g_pl[(pbase + c) * BQ + row] * wc[c];
    }
    const float inv = 1.0f / L;

    float acc[32];
    #pragma unroll
    for (int k = 0; k < 32; ++k) acc[k] = 0.f;
    for (int c = 0; c < nc; ++c) {
        const float* Pb = g_pO + (size_t)(pbase + c) * (BQ * 64) + row * 64 + col0;
        const float wcv = wc[c];
        #pragma unroll
        for (int k4 = 0; k4 < 8; ++k4) {
            float4 f = *(const float4*)(Pb + k4 * 4);
            acc[k4*4+0] += wcv * f.x;  acc[k4*4+1] += wcv * f.y;
            acc[k4*4+2] += wcv * f.z;  acc[k4*4+3] += wcv * f.w;
        }
    }
    float* Ob = O + ((size_t)b * SEQ + bq * BQ + row) * 64 + col0;
    #pragma unroll
    for (int k4 = 0; k4 < 8; ++k4)
        *(float4*)(Ob + k4 * 4) = make_float4(acc[k4*4+0]*inv, acc[k4*4+1]*inv,
                                              acc[k4*4+2]*inv, acc[k4*4+3]*inv);
}

extern "C" void kernel_launch(void* const* d_in, const int* in_sizes, int n_in,
                              void* d_out, int out_size)
{
    const float* Q = (const float*)d_in[0];
    const float* K = (const float*)d_in[1];
    const float* V = (const float*)d_in[2];
    const float* R = (const float*)d_in[3];
    float* O = (float*)d_out;

    preconvert<<<1024, 256>>>(K, V, R);

    cudaFuncSetAttribute(attn_relpos_mma,
                         cudaFuncAttributeMaxDynamicSharedMemorySize, SMEM_BYTES);
    attn_relpos_mma<<<dim3(40, BSZ), NT, SMEM_BYTES>>>(Q);

    combine<<<dim3(16, BSZ), NT>>>(O);
}